// round 6
// baseline (speedup 1.0000x reference)
#include <cuda_runtime.h>
#include <cstdint>

// ---------------------------------------------------------------------------
// B=32768, N=17 joints, D=2, K=3, H=64 (k/w MLPs), 2H=128 (b MLP)
// Outputs (flattened float32): out (B,N,K,5) | k_js (B,N) | mask (B,N,K)
// ---------------------------------------------------------------------------
#define NB        32768
#define NJ        17
#define TILE_B    32
#define NTILES    (NB / TILE_B)          // 1024
#define NPAIRS    (NTILES / 2)           // 512
#define NBJ       128                    // blocks per joint (128*4 warps = 512 pairs)
#define NWARPS    4                      // warps per block

#define JSTRIDE   2836                   // floats per joint in packed weights
#define WFLOATS   (NJ * JSTRIDE)

// packed per-joint layout (floats):
//  [0,384):    kMLP rows, 32 rows x 12: [W1d0 pair, W1d1 pair | W2o0, W2o1 | W2o2, b1]
//  [384,768):  wMLP rows, same
//  [768,2816): bMLP rows, 64 rows x 32: [W1 pairs(4) | W2 o0..o11 pairs (24) | b1 pair, pad]
//  [2816,2819): kb2[3]  [2819,2822): wb2[3]  [2822,2834): bb2[12]
#define SEC_W     384
#define SEC_B     768
#define OFF_KB2   2816
#define OFF_WB2   2819
#define OFF_BB2   2822

#define KJS_OFF     8355840ull           // B*N*K*5
#define MASK_OFF    8912896ull

typedef unsigned long long ull;

static __device__ __forceinline__ ull pk2(float lo, float hi) {
    ull r; asm("mov.b64 %0,{%1,%2};" : "=l"(r) : "f"(lo), "f"(hi)); return r;
}
static __device__ __forceinline__ ull fma2(ull a, ull b, ull c) {
    ull d; asm("fma.rn.f32x2 %0,%1,%2,%3;" : "=l"(d) : "l"(a), "l"(b), "l"(c)); return d;
}
static __device__ __forceinline__ ull relu2(ull g) {
    float lo, hi; asm("mov.b64 {%0,%1},%2;" : "=f"(lo), "=f"(hi) : "l"(g));
    lo = fmaxf(lo, 0.f); hi = fmaxf(hi, 0.f);
    ull r; asm("mov.b64 %0,{%1,%2};" : "=l"(r) : "f"(lo), "f"(hi)); return r;
}
static __device__ __forceinline__ float rsum2(ull a) {
    float lo, hi; asm("mov.b64 {%0,%1},%2;" : "=f"(lo), "=f"(hi) : "l"(a));
    return lo + hi;
}

__device__ __align__(16) float g_packed[WFLOATS];

// ---------------------------------------------------------------------------
// Setup kernel: pack weights into f32x2-pair rows (17 blocks x 128 threads).
// ---------------------------------------------------------------------------
__global__ void pack_weights(
    const float* __restrict__ kW1, const float* __restrict__ kb1,
    const float* __restrict__ kW2, const float* __restrict__ kb2,
    const float* __restrict__ wW1, const float* __restrict__ wb1,
    const float* __restrict__ wW2, const float* __restrict__ wb2,
    const float* __restrict__ bW1, const float* __restrict__ bb1,
    const float* __restrict__ bW2, const float* __restrict__ bb2)
{
    const int n = blockIdx.x;
    const int t = threadIdx.x;
    float* dst = g_packed + n * JSTRIDE;

    if (t < 32) {                       // kMLP row jp = t
        const int jp = t, j = 2 * jp;
        float* r = dst + jp * 12;
        r[0] = kW1[n * 128 + j];          r[1] = kW1[n * 128 + j + 1];
        r[2] = kW1[n * 128 + 64 + j];     r[3] = kW1[n * 128 + 64 + j + 1];
        #pragma unroll
        for (int o = 0; o < 3; o++) {
            r[4 + 2 * o] = kW2[n * 192 + j * 3 + o];
            r[5 + 2 * o] = kW2[n * 192 + (j + 1) * 3 + o];
        }
        r[10] = kb1[n * 64 + j];          r[11] = kb1[n * 64 + j + 1];
    } else if (t < 64) {                // wMLP row jp = t-32
        const int jp = t - 32, j = 2 * jp;
        float* r = dst + SEC_W + jp * 12;
        r[0] = wW1[n * 128 + j];          r[1] = wW1[n * 128 + j + 1];
        r[2] = wW1[n * 128 + 64 + j];     r[3] = wW1[n * 128 + 64 + j + 1];
        #pragma unroll
        for (int o = 0; o < 3; o++) {
            r[4 + 2 * o] = wW2[n * 192 + j * 3 + o];
            r[5 + 2 * o] = wW2[n * 192 + (j + 1) * 3 + o];
        }
        r[10] = wb1[n * 64 + j];          r[11] = wb1[n * 64 + j + 1];
    } else {                            // bMLP row jp = t-64
        const int jp = t - 64, j = 2 * jp;
        float* r = dst + SEC_B + jp * 32;
        r[0] = bW1[n * 256 + j];          r[1] = bW1[n * 256 + j + 1];
        r[2] = bW1[n * 256 + 128 + j];    r[3] = bW1[n * 256 + 128 + j + 1];
        #pragma unroll
        for (int o = 0; o < 12; o++) {
            r[4 + 2 * o] = bW2[n * 1536 + j * 12 + o];
            r[5 + 2 * o] = bW2[n * 1536 + (j + 1) * 12 + o];
        }
        r[28] = bb1[n * 128 + j];         r[29] = bb1[n * 128 + j + 1];
        r[30] = 0.f; r[31] = 0.f;
    }
    if (t == 0) {
        #pragma unroll
        for (int o = 0; o < 3; o++)  { dst[OFF_KB2 + o] = kb2[n * 3 + o];
                                       dst[OFF_WB2 + o] = wb2[n * 3 + o]; }
        #pragma unroll
        for (int o = 0; o < 12; o++)   dst[OFF_BB2 + o] = bb2[n * 12 + o];
    }
}

// Per-point epilogue: argmax, softmax, exp(sigma), stable descending sort.
// kl/wl are reloaded from the per-thread smem stash (stk/stw).
static __device__ __forceinline__ void finish(const float* __restrict__ stk,
                                              const float* __restrict__ stw,
                                              const float pv[12],
                                              float v[15], int& am)
{
    const float kl0 = stk[0], kl1 = stk[1], kl2 = stk[2];
    am = 0; float bm = kl0;
    if (kl1 > bm) { bm = kl1; am = 1; }
    if (kl2 > bm) { bm = kl2; am = 2; }

    const float wl0 = stw[0], wl1 = stw[1], wl2 = stw[2];
    float m  = fmaxf(wl0, fmaxf(wl1, wl2));
    float e0 = expf(wl0 - m), e1 = expf(wl1 - m), e2 = expf(wl2 - m);
    float inv = 1.0f / (e0 + e1 + e2);
    float wv[3] = { e0 * inv, e1 * inv, e2 * inv };

    float4 pl[3]; float ws[3];
    #pragma unroll
    for (int k = 0; k < 3; k++) {
        pl[k] = make_float4(pv[4 * k], pv[4 * k + 1],
                            expf(pv[4 * k + 2]), expf(pv[4 * k + 3]));
        ws[k] = wv[k];
    }
    // stable descending sort by w (strict >): matches stable jnp.argsort(-w)
    #define CSWAP(i_, j_)                                               \
        if (ws[j_] > ws[i_]) {                                          \
            float tw = ws[i_]; ws[i_] = ws[j_]; ws[j_] = tw;            \
            float4 tp = pl[i_]; pl[i_] = pl[j_]; pl[j_] = tp;           \
        }
    CSWAP(0, 1) CSWAP(1, 2) CSWAP(0, 1)
    #undef CSWAP

    #pragma unroll
    for (int k = 0; k < 3; k++) {
        v[5 * k + 0] = wv[k];
        v[5 * k + 1] = pl[k].x;
        v[5 * k + 2] = pl[k].y;
        v[5 * k + 3] = pl[k].z;
        v[5 * k + 4] = pl[k].w;
    }
}

// ---------------------------------------------------------------------------
// Main kernel: 128 threads (4 warps), 8 blocks/SM -> 32 warps/SM.
// Each warp handles exactly ONE pair of tiles (2 points/thread).
// kl/wl logits stashed to smem across the bMLP phase to cut live registers.
// ---------------------------------------------------------------------------
__global__ void __launch_bounds__(128, 8)
mlp_main(const float* __restrict__ pred, float* __restrict__ out)
{
    __shared__ float swt[JSTRIDE];                 // this joint's packed weights
    __shared__ float sStage[NWARPS][32 * 17];      // per-warp staging, pad 17
    __shared__ float sKW[NWARPS][32 * 13];         // kl/wl stash, pad 13

    const int joint = blockIdx.x % NJ;
    const int blk   = blockIdx.x / NJ;             // 0..NBJ-1
    const int wid   = threadIdx.x >> 5;
    const int lane  = threadIdx.x & 31;

    {   // stage this joint's weights into smem (coalesced float4)
        const float4* src = (const float4*)(g_packed + joint * JSTRIDE);
        float4* dst = (float4*)swt;
        #pragma unroll
        for (int i = threadIdx.x; i < JSTRIDE / 4; i += 128) dst[i] = src[i];
    }
    __syncthreads();

    float* myStage = sStage[wid];
    float* st = sKW[wid] + lane * 13;   // 12 floats per thread + pad
    const int j15 = lane & 15;
    const int hi  = lane >> 4;          // 0 for lanes 0-15, 1 for 16-31

    const int pr = blk * NWARPS + wid;  // 0..511, exact cover of all pairs
    const int ta = 2 * pr, tb = ta + 1;
    const int ba = ta * TILE_B + lane;
    const int bb = tb * TILE_B + lane;

    const float2 xa = *(const float2*)(pred + ((size_t)ba * NJ + joint) * 2);
    const float2 xb = *(const float2*)(pred + ((size_t)bb * NJ + joint) * 2);
    const ull X0a = pk2(xa.x, xa.x), X1a = pk2(xa.y, xa.y);
    const ull X0b = pk2(xb.x, xb.x), X1b = pk2(xb.y, xb.y);

    // ---- fused kMLP + wMLP (shared X, 12 independent acc chains) ----
    {
        ull ka0 = 0, ka1 = 0, ka2 = 0, kc0 = 0, kc1 = 0, kc2 = 0;
        ull wa0 = 0, wa1 = 0, wa2 = 0, wc0 = 0, wc1 = 0, wc2 = 0;
        #pragma unroll 4
        for (int jp = 0; jp < 32; jp++) {
            const float* rk = swt + jp * 12;
            const float* rw = swt + SEC_W + jp * 12;
            {
                ulonglong2 q0 = *(const ulonglong2*)(rk);
                ulonglong2 q1 = *(const ulonglong2*)(rk + 4);
                ulonglong2 q2 = *(const ulonglong2*)(rk + 8);
                ull ha = relu2(fma2(X0a, q0.x, fma2(X1a, q0.y, q2.y)));
                ull hb = relu2(fma2(X0b, q0.x, fma2(X1b, q0.y, q2.y)));
                ka0 = fma2(ha, q1.x, ka0);  kc0 = fma2(hb, q1.x, kc0);
                ka1 = fma2(ha, q1.y, ka1);  kc1 = fma2(hb, q1.y, kc1);
                ka2 = fma2(ha, q2.x, ka2);  kc2 = fma2(hb, q2.x, kc2);
            }
            {
                ulonglong2 q0 = *(const ulonglong2*)(rw);
                ulonglong2 q1 = *(const ulonglong2*)(rw + 4);
                ulonglong2 q2 = *(const ulonglong2*)(rw + 8);
                ull ha = relu2(fma2(X0a, q0.x, fma2(X1a, q0.y, q2.y)));
                ull hb = relu2(fma2(X0b, q0.x, fma2(X1b, q0.y, q2.y)));
                wa0 = fma2(ha, q1.x, wa0);  wc0 = fma2(hb, q1.x, wc0);
                wa1 = fma2(ha, q1.y, wa1);  wc1 = fma2(hb, q1.y, wc1);
                wa2 = fma2(ha, q2.x, wa2);  wc2 = fma2(hb, q2.x, wc2);
            }
        }
        // stash logits (+bias) to smem: frees 12 registers across bMLP
        const float kb2a = swt[OFF_KB2], kb2b = swt[OFF_KB2 + 1], kb2c = swt[OFF_KB2 + 2];
        const float wb2a = swt[OFF_WB2], wb2b = swt[OFF_WB2 + 1], wb2c = swt[OFF_WB2 + 2];
        st[0]  = rsum2(ka0) + kb2a; st[1]  = rsum2(ka1) + kb2b; st[2]  = rsum2(ka2) + kb2c;
        st[3]  = rsum2(wa0) + wb2a; st[4]  = rsum2(wa1) + wb2b; st[5]  = rsum2(wa2) + wb2c;
        st[6]  = rsum2(kc0) + kb2a; st[7]  = rsum2(kc1) + kb2b; st[8]  = rsum2(kc2) + kb2c;
        st[9]  = rsum2(wc0) + wb2a; st[10] = rsum2(wc1) + wb2b; st[11] = rsum2(wc2) + wb2c;
    }

    // ---- bMLP (2 -> 128 -> 12), dual point, weights loaded once ----
    ull acca[12], accb[12];
    #pragma unroll
    for (int o = 0; o < 12; o++) { acca[o] = 0; accb[o] = 0; }
    #pragma unroll 2
    for (int jp = 0; jp < 64; jp++) {
        const float* r = swt + SEC_B + jp * 32;
        ulonglong2 q0 = *(const ulonglong2*)(r);
        ull cb = *(const ull*)(r + 28);
        ull ha = relu2(fma2(X0a, q0.x, fma2(X1a, q0.y, cb)));
        ull hb = relu2(fma2(X0b, q0.x, fma2(X1b, q0.y, cb)));
        ulonglong2 q1 = *(const ulonglong2*)(r + 4);
        acca[0]  = fma2(ha, q1.x, acca[0]);  accb[0]  = fma2(hb, q1.x, accb[0]);
        acca[1]  = fma2(ha, q1.y, acca[1]);  accb[1]  = fma2(hb, q1.y, accb[1]);
        ulonglong2 q2 = *(const ulonglong2*)(r + 8);
        acca[2]  = fma2(ha, q2.x, acca[2]);  accb[2]  = fma2(hb, q2.x, accb[2]);
        acca[3]  = fma2(ha, q2.y, acca[3]);  accb[3]  = fma2(hb, q2.y, accb[3]);
        ulonglong2 q3 = *(const ulonglong2*)(r + 12);
        acca[4]  = fma2(ha, q3.x, acca[4]);  accb[4]  = fma2(hb, q3.x, accb[4]);
        acca[5]  = fma2(ha, q3.y, acca[5]);  accb[5]  = fma2(hb, q3.y, accb[5]);
        ulonglong2 q4 = *(const ulonglong2*)(r + 16);
        acca[6]  = fma2(ha, q4.x, acca[6]);  accb[6]  = fma2(hb, q4.x, accb[6]);
        acca[7]  = fma2(ha, q4.y, acca[7]);  accb[7]  = fma2(hb, q4.y, accb[7]);
        ulonglong2 q5 = *(const ulonglong2*)(r + 20);
        acca[8]  = fma2(ha, q5.x, acca[8]);  accb[8]  = fma2(hb, q5.x, accb[8]);
        acca[9]  = fma2(ha, q5.y, acca[9]);  accb[9]  = fma2(hb, q5.y, accb[9]);
        ulonglong2 q6 = *(const ulonglong2*)(r + 24);
        acca[10] = fma2(ha, q6.x, acca[10]); accb[10] = fma2(hb, q6.x, accb[10]);
        acca[11] = fma2(ha, q6.y, acca[11]); accb[11] = fma2(hb, q6.y, accb[11]);
    }
    float pva[12], pvb[12];
    #pragma unroll
    for (int o = 0; o < 12; o++) {
        const float bias = swt[OFF_BB2 + o];
        pva[o] = rsum2(acca[o]) + bias;
        pvb[o] = rsum2(accb[o]) + bias;
    }

    // ---- tile a: epilogue + stage + flush ----
    {
        float va[15]; int ama;
        finish(st, st + 3, pva, va, ama);
        float* op = myStage + lane * 17;
        #pragma unroll
        for (int k = 0; k < 15; k++) op[k] = va[k];
        const size_t pidx = (size_t)ba * NJ + joint;
        out[KJS_OFF + pidx] = (float)(ama + 1);
        float* gm = out + MASK_OFF + pidx * 3;
        gm[0] = 1.0f;
        gm[1] = (ama >= 1) ? 1.0f : 0.0f;
        gm[2] = (ama >= 2) ? 1.0f : 0.0f;
        __syncwarp();
        const size_t base = (size_t)ta * (TILE_B * NJ * 15) + (size_t)joint * 15;
        #pragma unroll
        for (int q = 0; q < 16; q++) {
            const int c = 2 * q + hi;
            if (j15 < 15)
                out[base + (size_t)c * (NJ * 15) + j15] = myStage[c * 17 + j15];
        }
        __syncwarp();
    }

    // ---- tile b: epilogue + stage + flush ----
    {
        float vb[15]; int amb;
        finish(st + 6, st + 9, pvb, vb, amb);
        float* op = myStage + lane * 17;
        #pragma unroll
        for (int k = 0; k < 15; k++) op[k] = vb[k];
        const size_t pidx = (size_t)bb * NJ + joint;
        out[KJS_OFF + pidx] = (float)(amb + 1);
        float* gm = out + MASK_OFF + pidx * 3;
        gm[0] = 1.0f;
        gm[1] = (amb >= 1) ? 1.0f : 0.0f;
        gm[2] = (amb >= 2) ? 1.0f : 0.0f;
        __syncwarp();
        const size_t base = (size_t)tb * (TILE_B * NJ * 15) + (size_t)joint * 15;
        #pragma unroll
        for (int q = 0; q < 16; q++) {
            const int c = 2 * q + hi;
            if (j15 < 15)
                out[base + (size_t)c * (NJ * 15) + j15] = myStage[c * 17 + j15];
        }
        __syncwarp();
    }
}

// ---------------------------------------------------------------------------
extern "C" void kernel_launch(void* const* d_in, const int* in_sizes, int n_in,
                              void* d_out, int out_size)
{
    const float* pred = (const float*)d_in[0];
    const float* kW1 = (const float*)d_in[1];
    const float* kb1 = (const float*)d_in[2];
    const float* kW2 = (const float*)d_in[3];
    const float* kb2 = (const float*)d_in[4];
    const float* wW1 = (const float*)d_in[5];
    const float* wb1 = (const float*)d_in[6];
    const float* wW2 = (const float*)d_in[7];
    const float* wb2 = (const float*)d_in[8];
    const float* bW1 = (const float*)d_in[9];
    const float* bb1 = (const float*)d_in[10];
    const float* bW2 = (const float*)d_in[11];
    const float* bb2 = (const float*)d_in[12];
    float* out = (float*)d_out;

    pack_weights<<<NJ, 128>>>(kW1, kb1, kW2, kb2,
                              wW1, wb1, wW2, wb2,
                              bW1, bb1, bW2, bb2);

    mlp_main<<<NJ * NBJ, 128>>>(pred, out);
}

// round 8
// speedup vs baseline: 1.7052x; 1.7052x over previous
#include <cuda_runtime.h>
#include <cstdint>

// ---------------------------------------------------------------------------
// B=32768, N=17 joints, D=2, K=3, H=64 (k/w MLPs), 2H=128 (b MLP)
// Outputs (flattened float32): out (B,N,K,5) | k_js (B,N) | mask (B,N,K)
// ---------------------------------------------------------------------------
#define NB        32768
#define NJ        17
#define TILE_B    32
#define NTILES    (NB / TILE_B)          // 1024
#define NPAIRS    (NTILES / 2)           // 512
#define NBJ       128                    // blocks per joint (128*4 warps = 512 pairs)
#define NWARPS    4                      // warps per block

#define JSTRIDE   2836                   // floats per joint in packed weights
#define WFLOATS   (NJ * JSTRIDE)

// packed per-joint layout (floats):
//  [0,384):    kMLP rows, 32 rows x 12: [W1d0 pair, W1d1 pair | W2o0, W2o1 | W2o2, b1]
//  [384,768):  wMLP rows, same
//  [768,2816): bMLP rows, 64 rows x 32: [W1 pairs(4) | W2 o0..o11 pairs (24) | b1 pair, pad]
//  [2816,2819): kb2[3]  [2819,2822): wb2[3]  [2822,2834): bb2[12]
#define SEC_W     384
#define SEC_B     768
#define OFF_KB2   2816
#define OFF_WB2   2819
#define OFF_BB2   2822

#define KJS_OFF     8355840ull           // B*N*K*5
#define MASK_OFF    8912896ull

typedef unsigned long long ull;

static __device__ __forceinline__ ull pk2(float lo, float hi) {
    ull r; asm("mov.b64 %0,{%1,%2};" : "=l"(r) : "f"(lo), "f"(hi)); return r;
}
static __device__ __forceinline__ ull fma2(ull a, ull b, ull c) {
    ull d; asm("fma.rn.f32x2 %0,%1,%2,%3;" : "=l"(d) : "l"(a), "l"(b), "l"(c)); return d;
}
static __device__ __forceinline__ ull relu2(ull g) {
    float lo, hi; asm("mov.b64 {%0,%1},%2;" : "=f"(lo), "=f"(hi) : "l"(g));
    lo = fmaxf(lo, 0.f); hi = fmaxf(hi, 0.f);
    ull r; asm("mov.b64 %0,{%1,%2};" : "=l"(r) : "f"(lo), "f"(hi)); return r;
}
static __device__ __forceinline__ float rsum2(ull a) {
    float lo, hi; asm("mov.b64 {%0,%1},%2;" : "=f"(lo), "=f"(hi) : "l"(a));
    return lo + hi;
}

__device__ __align__(16) float g_packed[WFLOATS];

// ---------------------------------------------------------------------------
// Setup kernel: pack weights into f32x2-pair rows (17 blocks x 128 threads).
// ---------------------------------------------------------------------------
__global__ void pack_weights(
    const float* __restrict__ kW1, const float* __restrict__ kb1,
    const float* __restrict__ kW2, const float* __restrict__ kb2,
    const float* __restrict__ wW1, const float* __restrict__ wb1,
    const float* __restrict__ wW2, const float* __restrict__ wb2,
    const float* __restrict__ bW1, const float* __restrict__ bb1,
    const float* __restrict__ bW2, const float* __restrict__ bb2)
{
    const int n = blockIdx.x;
    const int t = threadIdx.x;
    float* dst = g_packed + n * JSTRIDE;

    if (t < 32) {                       // kMLP row jp = t
        const int jp = t, j = 2 * jp;
        float* r = dst + jp * 12;
        r[0] = kW1[n * 128 + j];          r[1] = kW1[n * 128 + j + 1];
        r[2] = kW1[n * 128 + 64 + j];     r[3] = kW1[n * 128 + 64 + j + 1];
        #pragma unroll
        for (int o = 0; o < 3; o++) {
            r[4 + 2 * o] = kW2[n * 192 + j * 3 + o];
            r[5 + 2 * o] = kW2[n * 192 + (j + 1) * 3 + o];
        }
        r[10] = kb1[n * 64 + j];          r[11] = kb1[n * 64 + j + 1];
    } else if (t < 64) {                // wMLP row jp = t-32
        const int jp = t - 32, j = 2 * jp;
        float* r = dst + SEC_W + jp * 12;
        r[0] = wW1[n * 128 + j];          r[1] = wW1[n * 128 + j + 1];
        r[2] = wW1[n * 128 + 64 + j];     r[3] = wW1[n * 128 + 64 + j + 1];
        #pragma unroll
        for (int o = 0; o < 3; o++) {
            r[4 + 2 * o] = wW2[n * 192 + j * 3 + o];
            r[5 + 2 * o] = wW2[n * 192 + (j + 1) * 3 + o];
        }
        r[10] = wb1[n * 64 + j];          r[11] = wb1[n * 64 + j + 1];
    } else {                            // bMLP row jp = t-64
        const int jp = t - 64, j = 2 * jp;
        float* r = dst + SEC_B + jp * 32;
        r[0] = bW1[n * 256 + j];          r[1] = bW1[n * 256 + j + 1];
        r[2] = bW1[n * 256 + 128 + j];    r[3] = bW1[n * 256 + 128 + j + 1];
        #pragma unroll
        for (int o = 0; o < 12; o++) {
            r[4 + 2 * o] = bW2[n * 1536 + j * 12 + o];
            r[5 + 2 * o] = bW2[n * 1536 + (j + 1) * 12 + o];
        }
        r[28] = bb1[n * 128 + j];         r[29] = bb1[n * 128 + j + 1];
        r[30] = 0.f; r[31] = 0.f;
    }
    if (t == 0) {
        #pragma unroll
        for (int o = 0; o < 3; o++)  { dst[OFF_KB2 + o] = kb2[n * 3 + o];
                                       dst[OFF_WB2 + o] = wb2[n * 3 + o]; }
        #pragma unroll
        for (int o = 0; o < 12; o++)   dst[OFF_BB2 + o] = bb2[n * 12 + o];
    }
}

// Per-point epilogue: argmax, softmax, exp(sigma), stable descending sort.
// kl/wl are reloaded from the per-thread smem stash (stk/stw).
static __device__ __forceinline__ void finish(const float* __restrict__ stk,
                                              const float* __restrict__ stw,
                                              const float pv[12],
                                              float v[15], int& am)
{
    const float kl0 = stk[0], kl1 = stk[1], kl2 = stk[2];
    am = 0; float bm = kl0;
    if (kl1 > bm) { bm = kl1; am = 1; }
    if (kl2 > bm) { bm = kl2; am = 2; }

    const float wl0 = stw[0], wl1 = stw[1], wl2 = stw[2];
    float m  = fmaxf(wl0, fmaxf(wl1, wl2));
    float e0 = expf(wl0 - m), e1 = expf(wl1 - m), e2 = expf(wl2 - m);
    float inv = 1.0f / (e0 + e1 + e2);
    float wv[3] = { e0 * inv, e1 * inv, e2 * inv };

    float4 pl[3]; float ws[3];
    #pragma unroll
    for (int k = 0; k < 3; k++) {
        pl[k] = make_float4(pv[4 * k], pv[4 * k + 1],
                            expf(pv[4 * k + 2]), expf(pv[4 * k + 3]));
        ws[k] = wv[k];
    }
    // stable descending sort by w (strict >): matches stable jnp.argsort(-w)
    #define CSWAP(i_, j_)                                               \
        if (ws[j_] > ws[i_]) {                                          \
            float tw = ws[i_]; ws[i_] = ws[j_]; ws[j_] = tw;            \
            float4 tp = pl[i_]; pl[i_] = pl[j_]; pl[j_] = tp;           \
        }
    CSWAP(0, 1) CSWAP(1, 2) CSWAP(0, 1)
    #undef CSWAP

    #pragma unroll
    for (int k = 0; k < 3; k++) {
        v[5 * k + 0] = wv[k];
        v[5 * k + 1] = pl[k].x;
        v[5 * k + 2] = pl[k].y;
        v[5 * k + 3] = pl[k].z;
        v[5 * k + 4] = pl[k].w;
    }
}

// ---------------------------------------------------------------------------
// Main kernel: 128 threads (4 warps), 8 blocks/SM -> 32 warps/SM.
// Each warp handles exactly ONE pair of tiles (2 points/thread).
// bMLP split into two output-half passes: 24 acc regs instead of 48,
// so the whole kernel fits ~64 regs without spilling hot state.
// ---------------------------------------------------------------------------
__global__ void __launch_bounds__(128, 8)
mlp_main(const float* __restrict__ pred, float* __restrict__ out)
{
    __shared__ float swt[JSTRIDE];                 // this joint's packed weights
    __shared__ float sStage[NWARPS][32 * 17];      // per-warp staging, pad 17
    __shared__ float sKW[NWARPS][32 * 13];         // kl/wl stash, pad 13

    const int joint = blockIdx.x % NJ;
    const int blk   = blockIdx.x / NJ;             // 0..NBJ-1
    const int wid   = threadIdx.x >> 5;
    const int lane  = threadIdx.x & 31;

    {   // stage this joint's weights into smem (coalesced float4)
        const float4* src = (const float4*)(g_packed + joint * JSTRIDE);
        float4* dst = (float4*)swt;
        #pragma unroll
        for (int i = threadIdx.x; i < JSTRIDE / 4; i += 128) dst[i] = src[i];
    }
    __syncthreads();

    float* myStage = sStage[wid];
    float* st = sKW[wid] + lane * 13;   // 12 floats per thread + pad
    const int j15 = lane & 15;
    const int hi  = lane >> 4;          // 0 for lanes 0-15, 1 for 16-31

    const int pr = blk * NWARPS + wid;  // 0..511, exact cover of all pairs
    const int ta = 2 * pr, tb = ta + 1;
    const int ba = ta * TILE_B + lane;
    const int bb = tb * TILE_B + lane;

    const float2 xa = *(const float2*)(pred + ((size_t)ba * NJ + joint) * 2);
    const float2 xb = *(const float2*)(pred + ((size_t)bb * NJ + joint) * 2);
    const ull X0a = pk2(xa.x, xa.x), X1a = pk2(xa.y, xa.y);
    const ull X0b = pk2(xb.x, xb.x), X1b = pk2(xb.y, xb.y);

    // ---- fused kMLP + wMLP (shared X, 12 independent acc chains) ----
    {
        ull ka0 = 0, ka1 = 0, ka2 = 0, kc0 = 0, kc1 = 0, kc2 = 0;
        ull wa0 = 0, wa1 = 0, wa2 = 0, wc0 = 0, wc1 = 0, wc2 = 0;
        #pragma unroll 4
        for (int jp = 0; jp < 32; jp++) {
            const float* rk = swt + jp * 12;
            const float* rw = swt + SEC_W + jp * 12;
            {
                ulonglong2 q0 = *(const ulonglong2*)(rk);
                ulonglong2 q1 = *(const ulonglong2*)(rk + 4);
                ulonglong2 q2 = *(const ulonglong2*)(rk + 8);
                ull ha = relu2(fma2(X0a, q0.x, fma2(X1a, q0.y, q2.y)));
                ull hb = relu2(fma2(X0b, q0.x, fma2(X1b, q0.y, q2.y)));
                ka0 = fma2(ha, q1.x, ka0);  kc0 = fma2(hb, q1.x, kc0);
                ka1 = fma2(ha, q1.y, ka1);  kc1 = fma2(hb, q1.y, kc1);
                ka2 = fma2(ha, q2.x, ka2);  kc2 = fma2(hb, q2.x, kc2);
            }
            {
                ulonglong2 q0 = *(const ulonglong2*)(rw);
                ulonglong2 q1 = *(const ulonglong2*)(rw + 4);
                ulonglong2 q2 = *(const ulonglong2*)(rw + 8);
                ull ha = relu2(fma2(X0a, q0.x, fma2(X1a, q0.y, q2.y)));
                ull hb = relu2(fma2(X0b, q0.x, fma2(X1b, q0.y, q2.y)));
                wa0 = fma2(ha, q1.x, wa0);  wc0 = fma2(hb, q1.x, wc0);
                wa1 = fma2(ha, q1.y, wa1);  wc1 = fma2(hb, q1.y, wc1);
                wa2 = fma2(ha, q2.x, wa2);  wc2 = fma2(hb, q2.x, wc2);
            }
        }
        // stash logits (+bias) to smem: frees 12 registers across bMLP
        const float kb2a = swt[OFF_KB2], kb2b = swt[OFF_KB2 + 1], kb2c = swt[OFF_KB2 + 2];
        const float wb2a = swt[OFF_WB2], wb2b = swt[OFF_WB2 + 1], wb2c = swt[OFF_WB2 + 2];
        st[0]  = rsum2(ka0) + kb2a; st[1]  = rsum2(ka1) + kb2b; st[2]  = rsum2(ka2) + kb2c;
        st[3]  = rsum2(wa0) + wb2a; st[4]  = rsum2(wa1) + wb2b; st[5]  = rsum2(wa2) + wb2c;
        st[6]  = rsum2(kc0) + kb2a; st[7]  = rsum2(kc1) + kb2b; st[8]  = rsum2(kc2) + kb2c;
        st[9]  = rsum2(wc0) + wb2a; st[10] = rsum2(wc1) + wb2b; st[11] = rsum2(wc2) + wb2c;
    }

    // ---- bMLP (2 -> 128 -> 12), dual point, split over outputs: two
    //      passes of 6 outputs each -> only 12 ull accumulators live ----
    float pva[12], pvb[12];
    #pragma unroll
    for (int pass = 0; pass < 2; pass++) {
        ull acca[6], accb[6];
        #pragma unroll
        for (int o = 0; o < 6; o++) { acca[o] = 0; accb[o] = 0; }
        #pragma unroll 2
        for (int jp = 0; jp < 64; jp++) {
            const float* r = swt + SEC_B + jp * 32;
            ulonglong2 q0 = *(const ulonglong2*)(r);        // W1 pairs
            ull cb = *(const ull*)(r + 28);                 // b1 pair
            ull ha = relu2(fma2(X0a, q0.x, fma2(X1a, q0.y, cb)));
            ull hb = relu2(fma2(X0b, q0.x, fma2(X1b, q0.y, cb)));
            const float* w = r + 4 + pass * 12;             // this pass's W2 half
            ulonglong2 p0 = *(const ulonglong2*)(w);
            acca[0] = fma2(ha, p0.x, acca[0]);  accb[0] = fma2(hb, p0.x, accb[0]);
            acca[1] = fma2(ha, p0.y, acca[1]);  accb[1] = fma2(hb, p0.y, accb[1]);
            ulonglong2 p1 = *(const ulonglong2*)(w + 4);
            acca[2] = fma2(ha, p1.x, acca[2]);  accb[2] = fma2(hb, p1.x, accb[2]);
            acca[3] = fma2(ha, p1.y, acca[3]);  accb[3] = fma2(hb, p1.y, accb[3]);
            ulonglong2 p2 = *(const ulonglong2*)(w + 8);
            acca[4] = fma2(ha, p2.x, acca[4]);  accb[4] = fma2(hb, p2.x, accb[4]);
            acca[5] = fma2(ha, p2.y, acca[5]);  accb[5] = fma2(hb, p2.y, accb[5]);
        }
        #pragma unroll
        for (int o = 0; o < 6; o++) {
            const float bias = swt[OFF_BB2 + pass * 6 + o];
            pva[pass * 6 + o] = rsum2(acca[o]) + bias;
            pvb[pass * 6 + o] = rsum2(accb[o]) + bias;
        }
    }

    // ---- tile a: epilogue + stage + flush ----
    {
        float va[15]; int ama;
        finish(st, st + 3, pva, va, ama);
        float* op = myStage + lane * 17;
        #pragma unroll
        for (int k = 0; k < 15; k++) op[k] = va[k];
        const size_t pidx = (size_t)ba * NJ + joint;
        out[KJS_OFF + pidx] = (float)(ama + 1);
        float* gm = out + MASK_OFF + pidx * 3;
        gm[0] = 1.0f;
        gm[1] = (ama >= 1) ? 1.0f : 0.0f;
        gm[2] = (ama >= 2) ? 1.0f : 0.0f;
        __syncwarp();
        const size_t base = (size_t)ta * (TILE_B * NJ * 15) + (size_t)joint * 15;
        #pragma unroll
        for (int q = 0; q < 16; q++) {
            const int c = 2 * q + hi;
            if (j15 < 15)
                out[base + (size_t)c * (NJ * 15) + j15] = myStage[c * 17 + j15];
        }
        __syncwarp();
    }

    // ---- tile b: epilogue + stage + flush ----
    {
        float vb[15]; int amb;
        finish(st + 6, st + 9, pvb, vb, amb);
        float* op = myStage + lane * 17;
        #pragma unroll
        for (int k = 0; k < 15; k++) op[k] = vb[k];
        const size_t pidx = (size_t)bb * NJ + joint;
        out[KJS_OFF + pidx] = (float)(amb + 1);
        float* gm = out + MASK_OFF + pidx * 3;
        gm[0] = 1.0f;
        gm[1] = (amb >= 1) ? 1.0f : 0.0f;
        gm[2] = (amb >= 2) ? 1.0f : 0.0f;
        __syncwarp();
        const size_t base = (size_t)tb * (TILE_B * NJ * 15) + (size_t)joint * 15;
        #pragma unroll
        for (int q = 0; q < 16; q++) {
            const int c = 2 * q + hi;
            if (j15 < 15)
                out[base + (size_t)c * (NJ * 15) + j15] = myStage[c * 17 + j15];
        }
        __syncwarp();
    }
}

// ---------------------------------------------------------------------------
extern "C" void kernel_launch(void* const* d_in, const int* in_sizes, int n_in,
                              void* d_out, int out_size)
{
    const float* pred = (const float*)d_in[0];
    const float* kW1 = (const float*)d_in[1];
    const float* kb1 = (const float*)d_in[2];
    const float* kW2 = (const float*)d_in[3];
    const float* kb2 = (const float*)d_in[4];
    const float* wW1 = (const float*)d_in[5];
    const float* wb1 = (const float*)d_in[6];
    const float* wW2 = (const float*)d_in[7];
    const float* wb2 = (const float*)d_in[8];
    const float* bW1 = (const float*)d_in[9];
    const float* bb1 = (const float*)d_in[10];
    const float* bW2 = (const float*)d_in[11];
    const float* bb2 = (const float*)d_in[12];
    float* out = (float*)d_out;

    pack_weights<<<NJ, 128>>>(kW1, kb1, kW2, kb2,
                              wW1, wb1, wW2, wb2,
                              bW1, bb1, bW2, bb2);

    mlp_main<<<NJ * NBJ, 128>>>(pred, out);
}

// round 9
// speedup vs baseline: 1.9226x; 1.1275x over previous
#include <cuda_runtime.h>
#include <cstdint>

// ---------------------------------------------------------------------------
// B=32768, N=17 joints, D=2, K=3, H=64 (k/w MLPs), 2H=128 (b MLP)
// Outputs (flattened float32): out (B,N,K,5) | k_js (B,N) | mask (B,N,K)
// ---------------------------------------------------------------------------
#define NB        32768
#define NJ        17
#define TILE_B    32
#define NTILES    (NB / TILE_B)          // 1024
#define NPAIRS    (NTILES / 2)           // 512
#define NBJ       128                    // blocks per joint (128*4 warps = 512 pairs)
#define NWARPS    4                      // warps per block

#define JSTRIDE   2836                   // floats per joint in packed weights
#define WFLOATS   (NJ * JSTRIDE)

// packed per-joint layout (floats):
//  [0,384):    kMLP rows, 32 rows x 12: [W1d0 pair, W1d1 pair | W2o0, W2o1 | W2o2, b1]
//  [384,768):  wMLP rows, same
//  [768,2816): bMLP rows, 64 rows x 32: [W1 pairs(4) | W2 o0..o11 pairs (24) | b1 pair, pad]
//  [2816,2819): kb2[3]  [2819,2822): wb2[3]  [2822,2834): bb2[12]
#define SEC_W     384
#define SEC_B     768
#define OFF_KB2   2816
#define OFF_WB2   2819
#define OFF_BB2   2822

#define KJS_OFF     8355840ull           // B*N*K*5
#define MASK_OFF    8912896ull

typedef unsigned long long ull;

static __device__ __forceinline__ ull pk2(float lo, float hi) {
    ull r; asm("mov.b64 %0,{%1,%2};" : "=l"(r) : "f"(lo), "f"(hi)); return r;
}
static __device__ __forceinline__ ull fma2(ull a, ull b, ull c) {
    ull d; asm("fma.rn.f32x2 %0,%1,%2,%3;" : "=l"(d) : "l"(a), "l"(b), "l"(c)); return d;
}
static __device__ __forceinline__ ull relu2(ull g) {
    float lo, hi; asm("mov.b64 {%0,%1},%2;" : "=f"(lo), "=f"(hi) : "l"(g));
    lo = fmaxf(lo, 0.f); hi = fmaxf(hi, 0.f);
    ull r; asm("mov.b64 %0,{%1,%2};" : "=l"(r) : "f"(lo), "f"(hi)); return r;
}
static __device__ __forceinline__ float rsum2(ull a) {
    float lo, hi; asm("mov.b64 {%0,%1},%2;" : "=f"(lo), "=f"(hi) : "l"(a));
    return lo + hi;
}

__device__ __align__(16) float g_packed[WFLOATS];

// ---------------------------------------------------------------------------
// Setup kernel: pack weights into f32x2-pair rows (17 blocks x 128 threads).
// ---------------------------------------------------------------------------
__global__ void pack_weights(
    const float* __restrict__ kW1, const float* __restrict__ kb1,
    const float* __restrict__ kW2, const float* __restrict__ kb2,
    const float* __restrict__ wW1, const float* __restrict__ wb1,
    const float* __restrict__ wW2, const float* __restrict__ wb2,
    const float* __restrict__ bW1, const float* __restrict__ bb1,
    const float* __restrict__ bW2, const float* __restrict__ bb2)
{
    const int n = blockIdx.x;
    const int t = threadIdx.x;
    float* dst = g_packed + n * JSTRIDE;

    if (t < 32) {                       // kMLP row jp = t
        const int jp = t, j = 2 * jp;
        float* r = dst + jp * 12;
        r[0] = kW1[n * 128 + j];          r[1] = kW1[n * 128 + j + 1];
        r[2] = kW1[n * 128 + 64 + j];     r[3] = kW1[n * 128 + 64 + j + 1];
        #pragma unroll
        for (int o = 0; o < 3; o++) {
            r[4 + 2 * o] = kW2[n * 192 + j * 3 + o];
            r[5 + 2 * o] = kW2[n * 192 + (j + 1) * 3 + o];
        }
        r[10] = kb1[n * 64 + j];          r[11] = kb1[n * 64 + j + 1];
    } else if (t < 64) {                // wMLP row jp = t-32
        const int jp = t - 32, j = 2 * jp;
        float* r = dst + SEC_W + jp * 12;
        r[0] = wW1[n * 128 + j];          r[1] = wW1[n * 128 + j + 1];
        r[2] = wW1[n * 128 + 64 + j];     r[3] = wW1[n * 128 + 64 + j + 1];
        #pragma unroll
        for (int o = 0; o < 3; o++) {
            r[4 + 2 * o] = wW2[n * 192 + j * 3 + o];
            r[5 + 2 * o] = wW2[n * 192 + (j + 1) * 3 + o];
        }
        r[10] = wb1[n * 64 + j];          r[11] = wb1[n * 64 + j + 1];
    } else {                            // bMLP row jp = t-64
        const int jp = t - 64, j = 2 * jp;
        float* r = dst + SEC_B + jp * 32;
        r[0] = bW1[n * 256 + j];          r[1] = bW1[n * 256 + j + 1];
        r[2] = bW1[n * 256 + 128 + j];    r[3] = bW1[n * 256 + 128 + j + 1];
        #pragma unroll
        for (int o = 0; o < 12; o++) {
            r[4 + 2 * o] = bW2[n * 1536 + j * 12 + o];
            r[5 + 2 * o] = bW2[n * 1536 + (j + 1) * 12 + o];
        }
        r[28] = bb1[n * 128 + j];         r[29] = bb1[n * 128 + j + 1];
        r[30] = 0.f; r[31] = 0.f;
    }
    if (t == 0) {
        #pragma unroll
        for (int o = 0; o < 3; o++)  { dst[OFF_KB2 + o] = kb2[n * 3 + o];
                                       dst[OFF_WB2 + o] = wb2[n * 3 + o]; }
        #pragma unroll
        for (int o = 0; o < 12; o++)   dst[OFF_BB2 + o] = bb2[n * 12 + o];
    }
}

// Per-point epilogue: argmax, softmax, exp(sigma), stable descending sort.
static __device__ __forceinline__ void finish(const float kl[3], const float wl[3],
                                              const float pv[12],
                                              float v[15], int& am)
{
    am = 0; float bm = kl[0];
    if (kl[1] > bm) { bm = kl[1]; am = 1; }
    if (kl[2] > bm) { bm = kl[2]; am = 2; }

    float m  = fmaxf(wl[0], fmaxf(wl[1], wl[2]));
    float e0 = expf(wl[0] - m), e1 = expf(wl[1] - m), e2 = expf(wl[2] - m);
    float inv = 1.0f / (e0 + e1 + e2);
    float wv[3] = { e0 * inv, e1 * inv, e2 * inv };

    float4 pl[3]; float ws[3];
    #pragma unroll
    for (int k = 0; k < 3; k++) {
        pl[k] = make_float4(pv[4 * k], pv[4 * k + 1],
                            expf(pv[4 * k + 2]), expf(pv[4 * k + 3]));
        ws[k] = wv[k];
    }
    // stable descending sort by w (strict >): matches stable jnp.argsort(-w)
    #define CSWAP(i_, j_)                                               \
        if (ws[j_] > ws[i_]) {                                          \
            float tw = ws[i_]; ws[i_] = ws[j_]; ws[j_] = tw;            \
            float4 tp = pl[i_]; pl[i_] = pl[j_]; pl[j_] = tp;           \
        }
    CSWAP(0, 1) CSWAP(1, 2) CSWAP(0, 1)
    #undef CSWAP

    #pragma unroll
    for (int k = 0; k < 3; k++) {
        v[5 * k + 0] = wv[k];
        v[5 * k + 1] = pl[k].x;
        v[5 * k + 2] = pl[k].y;
        v[5 * k + 3] = pl[k].z;
        v[5 * k + 4] = pl[k].w;
    }
}

// ---------------------------------------------------------------------------
// Main kernel: 128 threads (4 warps), 6 blocks/SM -> 24 warps/SM.
// Each warp handles exactly ONE pair of tiles (2 points/thread).
// k+w MLPs fused (12 independent acc chains); bMLP unsplit, unroll 4.
// ---------------------------------------------------------------------------
__global__ void __launch_bounds__(128, 6)
mlp_main(const float* __restrict__ pred, float* __restrict__ out)
{
    __shared__ float swt[JSTRIDE];                 // this joint's packed weights
    __shared__ float sStage[NWARPS][32 * 17];      // per-warp staging, pad 17

    const int joint = blockIdx.x % NJ;
    const int blk   = blockIdx.x / NJ;             // 0..NBJ-1
    const int wid   = threadIdx.x >> 5;
    const int lane  = threadIdx.x & 31;

    {   // stage this joint's weights into smem (coalesced float4)
        const float4* src = (const float4*)(g_packed + joint * JSTRIDE);
        float4* dst = (float4*)swt;
        #pragma unroll
        for (int i = threadIdx.x; i < JSTRIDE / 4; i += 128) dst[i] = src[i];
    }
    __syncthreads();

    float* myStage = sStage[wid];
    const int j15 = lane & 15;
    const int hi  = lane >> 4;          // 0 for lanes 0-15, 1 for 16-31

    const int pr = blk * NWARPS + wid;  // 0..511, exact cover of all pairs
    const int ta = 2 * pr, tb = ta + 1;
    const int ba = ta * TILE_B + lane;
    const int bb = tb * TILE_B + lane;

    const float2 xa = *(const float2*)(pred + ((size_t)ba * NJ + joint) * 2);
    const float2 xb = *(const float2*)(pred + ((size_t)bb * NJ + joint) * 2);
    const ull X0a = pk2(xa.x, xa.x), X1a = pk2(xa.y, xa.y);
    const ull X0b = pk2(xb.x, xb.x), X1b = pk2(xb.y, xb.y);

    // ---- fused kMLP + wMLP: 12 independent acc chains ----
    float kla[3], klb[3], wla[3], wlb[3];
    {
        ull ka0 = 0, ka1 = 0, ka2 = 0, kc0 = 0, kc1 = 0, kc2 = 0;
        ull wa0 = 0, wa1 = 0, wa2 = 0, wc0 = 0, wc1 = 0, wc2 = 0;
        #pragma unroll 4
        for (int jp = 0; jp < 32; jp++) {
            const float* rk = swt + jp * 12;
            const float* rw = swt + SEC_W + jp * 12;
            {
                ulonglong2 q0 = *(const ulonglong2*)(rk);       // W1 d0,d1 pairs
                ulonglong2 q1 = *(const ulonglong2*)(rk + 4);   // W2 o0,o1
                ulonglong2 q2 = *(const ulonglong2*)(rk + 8);   // W2 o2, b1
                ull ha = relu2(fma2(X0a, q0.x, fma2(X1a, q0.y, q2.y)));
                ull hb = relu2(fma2(X0b, q0.x, fma2(X1b, q0.y, q2.y)));
                ka0 = fma2(ha, q1.x, ka0);  kc0 = fma2(hb, q1.x, kc0);
                ka1 = fma2(ha, q1.y, ka1);  kc1 = fma2(hb, q1.y, kc1);
                ka2 = fma2(ha, q2.x, ka2);  kc2 = fma2(hb, q2.x, kc2);
            }
            {
                ulonglong2 q0 = *(const ulonglong2*)(rw);
                ulonglong2 q1 = *(const ulonglong2*)(rw + 4);
                ulonglong2 q2 = *(const ulonglong2*)(rw + 8);
                ull ha = relu2(fma2(X0a, q0.x, fma2(X1a, q0.y, q2.y)));
                ull hb = relu2(fma2(X0b, q0.x, fma2(X1b, q0.y, q2.y)));
                wa0 = fma2(ha, q1.x, wa0);  wc0 = fma2(hb, q1.x, wc0);
                wa1 = fma2(ha, q1.y, wa1);  wc1 = fma2(hb, q1.y, wc1);
                wa2 = fma2(ha, q2.x, wa2);  wc2 = fma2(hb, q2.x, wc2);
            }
        }
        const float kb2a = swt[OFF_KB2], kb2b = swt[OFF_KB2 + 1], kb2c = swt[OFF_KB2 + 2];
        const float wb2a = swt[OFF_WB2], wb2b = swt[OFF_WB2 + 1], wb2c = swt[OFF_WB2 + 2];
        kla[0] = rsum2(ka0) + kb2a; kla[1] = rsum2(ka1) + kb2b; kla[2] = rsum2(ka2) + kb2c;
        klb[0] = rsum2(kc0) + kb2a; klb[1] = rsum2(kc1) + kb2b; klb[2] = rsum2(kc2) + kb2c;
        wla[0] = rsum2(wa0) + wb2a; wla[1] = rsum2(wa1) + wb2b; wla[2] = rsum2(wa2) + wb2c;
        wlb[0] = rsum2(wc0) + wb2a; wlb[1] = rsum2(wc1) + wb2b; wlb[2] = rsum2(wc2) + wb2c;
    }

    // ---- bMLP (2 -> 128 -> 12), dual point, weights loaded once ----
    ull acca[12], accb[12];
    #pragma unroll
    for (int o = 0; o < 12; o++) { acca[o] = 0; accb[o] = 0; }
    #pragma unroll 4
    for (int jp = 0; jp < 64; jp++) {
        const float* r = swt + SEC_B + jp * 32;
        ulonglong2 q0 = *(const ulonglong2*)(r);
        ull cb = *(const ull*)(r + 28);
        ull ha = relu2(fma2(X0a, q0.x, fma2(X1a, q0.y, cb)));
        ull hb = relu2(fma2(X0b, q0.x, fma2(X1b, q0.y, cb)));
        ulonglong2 q1 = *(const ulonglong2*)(r + 4);
        acca[0]  = fma2(ha, q1.x, acca[0]);  accb[0]  = fma2(hb, q1.x, accb[0]);
        acca[1]  = fma2(ha, q1.y, acca[1]);  accb[1]  = fma2(hb, q1.y, accb[1]);
        ulonglong2 q2 = *(const ulonglong2*)(r + 8);
        acca[2]  = fma2(ha, q2.x, acca[2]);  accb[2]  = fma2(hb, q2.x, accb[2]);
        acca[3]  = fma2(ha, q2.y, acca[3]);  accb[3]  = fma2(hb, q2.y, accb[3]);
        ulonglong2 q3 = *(const ulonglong2*)(r + 12);
        acca[4]  = fma2(ha, q3.x, acca[4]);  accb[4]  = fma2(hb, q3.x, accb[4]);
        acca[5]  = fma2(ha, q3.y, acca[5]);  accb[5]  = fma2(hb, q3.y, accb[5]);
        ulonglong2 q4 = *(const ulonglong2*)(r + 16);
        acca[6]  = fma2(ha, q4.x, acca[6]);  accb[6]  = fma2(hb, q4.x, accb[6]);
        acca[7]  = fma2(ha, q4.y, acca[7]);  accb[7]  = fma2(hb, q4.y, accb[7]);
        ulonglong2 q5 = *(const ulonglong2*)(r + 20);
        acca[8]  = fma2(ha, q5.x, acca[8]);  accb[8]  = fma2(hb, q5.x, accb[8]);
        acca[9]  = fma2(ha, q5.y, acca[9]);  accb[9]  = fma2(hb, q5.y, accb[9]);
        ulonglong2 q6 = *(const ulonglong2*)(r + 24);
        acca[10] = fma2(ha, q6.x, acca[10]); accb[10] = fma2(hb, q6.x, accb[10]);
        acca[11] = fma2(ha, q6.y, acca[11]); accb[11] = fma2(hb, q6.y, accb[11]);
    }
    float pva[12], pvb[12];
    #pragma unroll
    for (int o = 0; o < 12; o++) {
        const float bias = swt[OFF_BB2 + o];
        pva[o] = rsum2(acca[o]) + bias;
        pvb[o] = rsum2(accb[o]) + bias;
    }

    // ---- tile a: epilogue + stage + flush ----
    {
        float va[15]; int ama;
        finish(kla, wla, pva, va, ama);
        float* op = myStage + lane * 17;
        #pragma unroll
        for (int k = 0; k < 15; k++) op[k] = va[k];
        const size_t pidx = (size_t)ba * NJ + joint;
        out[KJS_OFF + pidx] = (float)(ama + 1);
        float* gm = out + MASK_OFF + pidx * 3;
        gm[0] = 1.0f;
        gm[1] = (ama >= 1) ? 1.0f : 0.0f;
        gm[2] = (ama >= 2) ? 1.0f : 0.0f;
        __syncwarp();
        const size_t base = (size_t)ta * (TILE_B * NJ * 15) + (size_t)joint * 15;
        #pragma unroll
        for (int q = 0; q < 16; q++) {
            const int c = 2 * q + hi;
            if (j15 < 15)
                out[base + (size_t)c * (NJ * 15) + j15] = myStage[c * 17 + j15];
        }
        __syncwarp();
    }

    // ---- tile b: epilogue + stage + flush ----
    {
        float vb[15]; int amb;
        finish(klb, wlb, pvb, vb, amb);
        float* op = myStage + lane * 17;
        #pragma unroll
        for (int k = 0; k < 15; k++) op[k] = vb[k];
        const size_t pidx = (size_t)bb * NJ + joint;
        out[KJS_OFF + pidx] = (float)(amb + 1);
        float* gm = out + MASK_OFF + pidx * 3;
        gm[0] = 1.0f;
        gm[1] = (amb >= 1) ? 1.0f : 0.0f;
        gm[2] = (amb >= 2) ? 1.0f : 0.0f;
        __syncwarp();
        const size_t base = (size_t)tb * (TILE_B * NJ * 15) + (size_t)joint * 15;
        #pragma unroll
        for (int q = 0; q < 16; q++) {
            const int c = 2 * q + hi;
            if (j15 < 15)
                out[base + (size_t)c * (NJ * 15) + j15] = myStage[c * 17 + j15];
        }
        __syncwarp();
    }
}

// ---------------------------------------------------------------------------
extern "C" void kernel_launch(void* const* d_in, const int* in_sizes, int n_in,
                              void* d_out, int out_size)
{
    const float* pred = (const float*)d_in[0];
    const float* kW1 = (const float*)d_in[1];
    const float* kb1 = (const float*)d_in[2];
    const float* kW2 = (const float*)d_in[3];
    const float* kb2 = (const float*)d_in[4];
    const float* wW1 = (const float*)d_in[5];
    const float* wb1 = (const float*)d_in[6];
    const float* wW2 = (const float*)d_in[7];
    const float* wb2 = (const float*)d_in[8];
    const float* bW1 = (const float*)d_in[9];
    const float* bb1 = (const float*)d_in[10];
    const float* bW2 = (const float*)d_in[11];
    const float* bb2 = (const float*)d_in[12];
    float* out = (float*)d_out;

    pack_weights<<<NJ, 128>>>(kW1, kb1, kW2, kb2,
                              wW1, wb1, wW2, wb2,
                              bW1, bb1, bW2, bb2);

    mlp_main<<<NJ * NBJ, 128>>>(pred, out);
}